// round 8
// baseline (speedup 1.0000x reference)
#include <cuda_runtime.h>
#include <cuda_bf16.h>
#include <math.h>
#include <stdint.h>

#define KTOK   77
#define BATCH  256
#define DMODEL 768
#define NPATCH 576
#define NROWS  (KTOK * BATCH)      // 19712

// ---- candidate lists (replace the 45 MB S matrix) ----
#define CAP 96
__device__ int   g_cnt[NROWS];     // zero-initialized at load; decode re-zeroes
__device__ int   g_cidx[(size_t)NROWS * CAP];
__device__ float g_cval[(size_t)NROWS * CAP];

// windows: collection (tile-local) must be >= decode filter window
#define CWIN_COLLECT 4.0f
#define CWIN_FILTER  3.5f

// ---------------- GEMM geometry (R7-proven, unchanged) ----------------
#define BM    96
#define BN    192
#define KC    32
#define NCH   (DMODEL / KC)      // 24
#define STRW  20                 // staging row stride (words)
#define AWRD  (BM * STRW)        // 1920
#define BWRD  (BN * STRW)        // 3840
#define BUFW  (AWRD + BWRD)      // 5760 words per stage
#define SSTR  100                // S tile row stride (words)
#define SWRD  (BM * SSTR)        // 9600
#define DYN_SMEM ((2 * BUFW + SWRD) * 4)   // 84,480 B

__device__ __forceinline__ void mma_bf16(float* c, const uint32_t* a, const uint32_t* b) {
    asm volatile(
        "mma.sync.aligned.m16n8k16.row.col.f32.bf16.bf16.f32 "
        "{%0,%1,%2,%3}, {%4,%5,%6,%7}, {%8,%9}, {%0,%1,%2,%3};"
        : "+f"(c[0]), "+f"(c[1]), "+f"(c[2]), "+f"(c[3])
        : "r"(a[0]), "r"(a[1]), "r"(a[2]), "r"(a[3]), "r"(b[0]), "r"(b[1]));
}
__device__ __forceinline__ uint32_t pack_bf2(float x, float y) {
    __nv_bfloat162 h = __floats2bfloat162_rn(x, y);
    return *(uint32_t*)&h;
}

__device__ __forceinline__ void ldg_chunk(const float* __restrict__ text,
                                          const float* __restrict__ vision,
                                          int b, int n0, int d0, int tid, uint2 rg[9]) {
#pragma unroll
    for (int it = 0; it < 9; ++it) {
        int q = tid + it * 256;
        float4 f;
        if (q < 768) {                       // A: 96 rows x 8 float4
            int r = q >> 3, f4 = q & 7;
            int rr = r < KTOK ? r : KTOK - 1;
            f = *(const float4*)&text[((size_t)rr * BATCH + b) * DMODEL + d0 + f4 * 4];
        } else {                             // B: 192 rows x 8 float4
            int q2 = q - 768;
            int r = q2 >> 3, f4 = q2 & 7;
            f = *(const float4*)&vision[((size_t)(n0 + r) * BATCH + b) * DMODEL + d0 + f4 * 4];
        }
        rg[it].x = pack_bf2(f.x, f.y);
        rg[it].y = pack_bf2(f.z, f.w);
    }
}

__device__ __forceinline__ void sts_chunk(uint32_t* As, uint32_t* Bs, int tid,
                                          const uint2 rg[9]) {
#pragma unroll
    for (int it = 0; it < 9; ++it) {
        int q = tid + it * 256;
        if (q < 768) {
            int r = q >> 3, f4 = q & 7;
            *(uint2*)(As + r * STRW + f4 * 2) = rg[it];
        } else {
            int q2 = q - 768;
            int r = q2 >> 3, f4 = q2 & 7;
            *(uint2*)(Bs + r * STRW + f4 * 2) = rg[it];
        }
    }
}

// ---------------- Kernel A: scores + candidate extraction (unchanged) ----------------
__global__ __launch_bounds__(256, 2)
void scores_mma_kernel(const float* __restrict__ text,
                       const float* __restrict__ vision) {
    extern __shared__ __align__(16) uint32_t sm[];
    uint32_t* Ssm = sm + 2 * BUFW;          // bf16 S tile, 96 x 192

    const int tid  = threadIdx.x;
    const int wid  = tid >> 5;
    const int lane = tid & 31;
    const int b    = blockIdx.y;
    const int n0   = blockIdx.x * BN;

    const int l4 = lane >> 2;
    const int lm = lane & 3;
    const int mb = (wid >> 2) * 48;
    const int nb = (wid & 3) * 48;

    float acc[3][6][4];
#pragma unroll
    for (int i = 0; i < 3; ++i)
#pragma unroll
        for (int j = 0; j < 6; ++j)
#pragma unroll
            for (int q = 0; q < 4; ++q) acc[i][j][q] = 0.f;

    uint2 rg[9];
    ldg_chunk(text, vision, b, n0, 0, tid, rg);
    sts_chunk(sm, sm + AWRD, tid, rg);
    __syncthreads();

    for (int c = 0; c < NCH; ++c) {
        if (c + 1 < NCH)
            ldg_chunk(text, vision, b, n0, (c + 1) * KC, tid, rg);

        const uint32_t* As = sm + (c & 1) * BUFW;
        const uint32_t* Bs = As + AWRD;

#pragma unroll
        for (int ks = 0; ks < 2; ++ks) {
            const int kw = ks * 8;
            uint32_t af[3][4], bf[6][2];
#pragma unroll
            for (int mf = 0; mf < 3; ++mf) {
                const uint32_t* p = As + (mb + mf * 16 + l4) * STRW + kw + lm;
                af[mf][0] = p[0];
                af[mf][1] = p[8 * STRW];
                af[mf][2] = p[4];
                af[mf][3] = p[8 * STRW + 4];
            }
#pragma unroll
            for (int nf = 0; nf < 6; ++nf) {
                const uint32_t* p = Bs + (nb + nf * 8 + l4) * STRW + kw + lm;
                bf[nf][0] = p[0];
                bf[nf][1] = p[4];
            }
#pragma unroll
            for (int mf = 0; mf < 3; ++mf)
#pragma unroll
                for (int nf = 0; nf < 6; ++nf)
                    mma_bf16(acc[mf][nf], af[mf], bf[nf]);
        }

        if (c + 1 < NCH) {
            uint32_t* nAs = sm + ((c + 1) & 1) * BUFW;
            sts_chunk(nAs, nAs + AWRD, tid, rg);
        }
        __syncthreads();
    }

#pragma unroll
    for (int mf = 0; mf < 3; ++mf) {
        const int m0 = mb + mf * 16 + l4;
#pragma unroll
        for (int nf = 0; nf < 6; ++nf) {
            const int colw = (nb + nf * 8 + 2 * lm) >> 1;
            Ssm[m0 * SSTR + colw]       = pack_bf2(acc[mf][nf][0], acc[mf][nf][1]);
            Ssm[(m0 + 8) * SSTR + colw] = pack_bf2(acc[mf][nf][2], acc[mf][nf][3]);
        }
    }
    __syncthreads();

    for (int k = wid; k < KTOK; k += 8) {
        float2 v[3];
        float m = -INFINITY;
#pragma unroll
        for (int i = 0; i < 3; ++i) {
            uint32_t w = Ssm[k * SSTR + lane + 32 * i];
            v[i] = __bfloat1622float2(*(__nv_bfloat162*)&w);
            m = fmaxf(m, fmaxf(v[i].x, v[i].y));
        }
#pragma unroll
        for (int o = 16; o; o >>= 1) m = fmaxf(m, __shfl_xor_sync(~0u, m, o));

        const float th = m - CWIN_COLLECT;
        const int row = b * KTOK + k;
#pragma unroll
        for (int i = 0; i < 3; ++i) {
            int n2 = n0 + ((lane + 32 * i) << 1);
            if (v[i].x >= th) {
                int p = atomicAdd(&g_cnt[row], 1);
                if (p < CAP) { g_cidx[(size_t)row * CAP + p] = n2;     g_cval[(size_t)row * CAP + p] = v[i].x; }
            }
            if (v[i].y >= th) {
                int p = atomicAdd(&g_cnt[row], 1);
                if (p < CAP) { g_cidx[(size_t)row * CAP + p] = n2 + 1; g_cval[(size_t)row * CAP + p] = v[i].y; }
            }
        }
    }
}

// ---------------- Kernel B: online-softmax candidate decode ----------------
// One warp per (b,k) row. Text row preloaded once; each candidate vision row
// is loaded ONCE into registers and used for both the exact fp32 dot and the
// weighted accumulation (running max/denominator rescaling, flash-style).
__global__ __launch_bounds__(256)
void decode_kernel(const float* __restrict__ text,
                   const float* __restrict__ vision,
                   float* __restrict__ out) {
    __shared__ int sidx[8][CAP];

    const int wid  = threadIdx.x >> 5;
    const int lane = threadIdx.x & 31;
    const int row  = blockIdx.x * 8 + wid;      // = b*77 + k
    if (row >= NROWS) return;
    const int b = row / KTOK;
    const int k = row % KTOK;

    int c = g_cnt[row];
    if (c > CAP) c = CAP;

    __shared__ float sval[8][CAP];
    for (int ci = lane; ci < c; ci += 32) {
        sidx[wid][ci] = g_cidx[(size_t)row * CAP + ci];
        sval[wid][ci] = g_cval[(size_t)row * CAP + ci];
    }
    if (lane == 0) g_cnt[row] = 0;     // reset for the next graph replay
    __syncwarp();

    // deterministic order: insertion sort by index, then filter vs approx max
    if (lane == 0) {
        for (int i = 1; i < c; ++i) {
            int   ix = sidx[wid][i];
            float vx = sval[wid][i];
            int j = i - 1;
            while (j >= 0 && sidx[wid][j] > ix) {
                sidx[wid][j + 1] = sidx[wid][j];
                sval[wid][j + 1] = sval[wid][j];
                --j;
            }
            sidx[wid][j + 1] = ix;
            sval[wid][j + 1] = vx;
        }
        float vmax = -INFINITY;
        for (int i = 0; i < c; ++i) vmax = fmaxf(vmax, sval[wid][i]);
        const float th = vmax - CWIN_FILTER;
        int w = 0;
        for (int i = 0; i < c; ++i)
            if (sval[wid][i] >= th) {
                sidx[wid][w] = sidx[wid][i];
                ++w;
            }
        sval[wid][CAP - 1] = __int_as_float(w);
    }
    __syncwarp();
    const int c2 = __float_as_int(sval[wid][CAP - 1]);

    // preload text row (24 floats/lane)
    const float* trow = text + ((size_t)k * BATCH + b) * DMODEL;
    float4 t4[6];
#pragma unroll
    for (int i = 0; i < 6; ++i)
        t4[i] = *(const float4*)&trow[(lane + 32 * i) << 2];

    // online softmax accumulation
    float m = -INFINITY, d = 0.f;
    float4 o4[6];
#pragma unroll
    for (int i = 0; i < 6; ++i) o4[i] = make_float4(0.f, 0.f, 0.f, 0.f);

    for (int ci = 0; ci < c2; ++ci) {
        const float* vrow = vision + ((size_t)sidx[wid][ci] * BATCH + b) * DMODEL;
        float4 v4[6];
        float s = 0.f;
#pragma unroll
        for (int i = 0; i < 6; ++i) {
            v4[i] = *(const float4*)&vrow[(lane + 32 * i) << 2];
            s = fmaf(t4[i].x, v4[i].x, s);
            s = fmaf(t4[i].y, v4[i].y, s);
            s = fmaf(t4[i].z, v4[i].z, s);
            s = fmaf(t4[i].w, v4[i].w, s);
        }
#pragma unroll
        for (int o = 16; o; o >>= 1) s += __shfl_xor_sync(~0u, s, o);   // all lanes

        if (s > m) {                       // rescale running state
            float r = (m == -INFINITY) ? 0.f : expf((m - s) * (1.0f / 0.07f));
            d *= r;
#pragma unroll
            for (int i = 0; i < 6; ++i) {
                o4[i].x *= r; o4[i].y *= r; o4[i].z *= r; o4[i].w *= r;
            }
            m = s;
        }
        float w = expf((s - m) * (1.0f / 0.07f));
        d += w;
#pragma unroll
        for (int i = 0; i < 6; ++i) {
            o4[i].x = fmaf(w, v4[i].x, o4[i].x);
            o4[i].y = fmaf(w, v4[i].y, o4[i].y);
            o4[i].z = fmaf(w, v4[i].z, o4[i].z);
            o4[i].w = fmaf(w, v4[i].w, o4[i].w);
        }
    }

    const float inv = 1.f / d;
    float* orow = out + ((size_t)k * BATCH + b) * DMODEL;
#pragma unroll
    for (int i = 0; i < 6; ++i) {
        float4 v;
        v.x = o4[i].x * inv; v.y = o4[i].y * inv;
        v.z = o4[i].z * inv; v.w = o4[i].w * inv;
        *(float4*)&orow[(lane + 32 * i) << 2] = v;
    }
}

// ---------------- launch ----------------
extern "C" void kernel_launch(void* const* d_in, const int* in_sizes, int n_in,
                              void* d_out, int out_size) {
    const float* text   = (const float*)d_in[0];
    const float* vision = (const float*)d_in[1];
    float* out          = (float*)d_out;

    cudaFuncSetAttribute(scores_mma_kernel,
                         cudaFuncAttributeMaxDynamicSharedMemorySize, DYN_SMEM);
    dim3 g1(NPATCH / BN, BATCH);                 // 3 x 256, x fastest => text L2 reuse
    scores_mma_kernel<<<g1, 256, DYN_SMEM>>>(text, vision);

    decode_kernel<<<(NROWS + 7) / 8, 256>>>(text, vision, out);
}